// round 2
// baseline (speedup 1.0000x reference)
#include <cuda_runtime.h>

#define HID 8192
#define BATCH 512
#define NIN 16
#define RANK 8
#define NOUT 4
#define HSPLIT 8   // H-chunks for k_rank / k_out
#define BSPLIT 4   // batch-chunks for k_update

// scratch (deterministic two-stage reductions, no atomics)
__device__ float g_u_part[HSPLIT][BATCH * RANK];
__device__ float g_u[BATCH * RANK];
__device__ float g_out_part[HSPLIT][BATCH * NOUT];

typedef unsigned long long ull;

__device__ __forceinline__ void ffma2(ull& d, ull a, ull b) {
    asm("fma.rn.f32x2 %0, %1, %2, %0;" : "+l"(d) : "l"(a), "l"(b));
}
__device__ __forceinline__ void unpack2(float& lo, float& hi, ull v) {
    asm("mov.b64 {%0, %1}, %2;" : "=f"(lo), "=f"(hi) : "l"(v));
}

// accurate tanh: ~1e-7 abs error
__device__ __forceinline__ float fast_tanh(float x) {
    float cx = fminf(fmaxf(x, -15.0f), 15.0f);
    float e = __expf(2.0f * cx);
    return __fdividef(e - 1.0f, e + 1.0f);
}

// ---------------------------------------------------------------------------
// K1: partial u over one H-chunk of 1024.
// grid = (BATCH/4, HSPLIT) = 1024 blocks, 256 threads, single pass, float4.
// ---------------------------------------------------------------------------
__global__ void __launch_bounds__(256) k_rank(const float* __restrict__ h,
                                              const float* __restrict__ R) {
    const int t = threadIdx.x;
    const int bbase = blockIdx.x * 4;
    const int hs = blockIdx.y;
    const int j = hs * (HID / HSPLIT) + t * 4;

    float4 r4[8];
#pragma unroll
    for (int r = 0; r < 8; r++)
        r4[r] = *(const float4*)(R + r * HID + j);

    float acc[4][8];
#pragma unroll
    for (int bl = 0; bl < 4; bl++) {
        float4 h4 = *(const float4*)(h + (bbase + bl) * HID + j);
        float t0 = __tanhf(h4.x);
        float t1 = __tanhf(h4.y);
        float t2 = __tanhf(h4.z);
        float t3 = __tanhf(h4.w);
#pragma unroll
        for (int r = 0; r < 8; r++) {
            float a = t0 * r4[r].x;
            a = fmaf(t1, r4[r].y, a);
            a = fmaf(t2, r4[r].z, a);
            a = fmaf(t3, r4[r].w, a);
            acc[bl][r] = a;
        }
    }

#pragma unroll
    for (int bl = 0; bl < 4; bl++)
#pragma unroll
        for (int r = 0; r < 8; r++)
#pragma unroll
            for (int off = 16; off > 0; off >>= 1)
                acc[bl][r] += __shfl_xor_sync(0xffffffffu, acc[bl][r], off);

    __shared__ float red[8][32];
    const int lane = t & 31, w = t >> 5;
    if (lane == 0) {
#pragma unroll
        for (int bl = 0; bl < 4; bl++)
#pragma unroll
            for (int r = 0; r < 8; r++)
                red[w][bl * 8 + r] = acc[bl][r];
    }
    __syncthreads();
    if (t < 32) {
        float s = 0.0f;
#pragma unroll
        for (int w2 = 0; w2 < 8; w2++) s += red[w2][t];
        const int bl = t >> 3, r = t & 7;
        g_u_part[hs][(bbase + bl) * RANK + r] = s;
    }
}

// ---------------------------------------------------------------------------
// K1b: combine u partials. 4096 outputs.
// ---------------------------------------------------------------------------
__global__ void __launch_bounds__(256) k_u_combine() {
    const int idx = blockIdx.x * 256 + threadIdx.x;
    if (idx < BATCH * RANK) {
        float s = 0.0f;
#pragma unroll
        for (int hs = 0; hs < HSPLIT; hs++) s += g_u_part[hs][idx];
        g_u[idx] = s * (1.0f / (float)HID);
    }
}

// ---------------------------------------------------------------------------
// K2: new_h = 0.9 h + 0.1 (input.W_in[j] + u.L[j])
// grid = (HID/64, BSPLIT) = 512 blocks. Thread owns 4 j-columns, weights in
// registers as f32x2 pairs; loops over 128 batch rows of its batch chunk.
// ---------------------------------------------------------------------------
__global__ void __launch_bounds__(256) k_update(const float* __restrict__ input,
                                                const float* __restrict__ hidden,
                                                const float* __restrict__ Win,
                                                const float* __restrict__ L,
                                                float* __restrict__ nh_out) {
    const int t = threadIdx.x;
    const int jg = t & 15;       // 16 groups of 4 j
    const int bs = t >> 4;       // 0..15
    const int j0 = blockIdx.x * 64 + jg * 4;
    const int b0 = blockIdx.y * (BATCH / BSPLIT);

    ull wj[4][8];   // W_in[j][0..15] as 8 pairs
    ull lj[4][4];   // L[j][0..7]     as 4 pairs
#pragma unroll
    for (int jj = 0; jj < 4; jj++) {
        const ull* wr = (const ull*)(Win + (j0 + jj) * NIN);
#pragma unroll
        for (int i = 0; i < 8; i++) wj[jj][i] = wr[i];
        const ull* lr = (const ull*)(L + (j0 + jj) * RANK);
#pragma unroll
        for (int r = 0; r < 4; r++) lj[jj][r] = lr[r];
    }

    for (int bi = bs; bi < BATCH / BSPLIT; bi += 16) {
        const int b = b0 + bi;
        const ull* ip = (const ull*)(input + b * NIN);
        ull ipr[8];
#pragma unroll
        for (int i = 0; i < 8; i++) ipr[i] = ip[i];
        const ull* up = (const ull*)(g_u + b * RANK);
        ull upr[4];
#pragma unroll
        for (int r = 0; r < 4; r++) upr[r] = up[r];

        float4 h4 = *(const float4*)(hidden + b * HID + j0);

        float res[4];
#pragma unroll
        for (int jj = 0; jj < 4; jj++) {
            ull acc = 0ULL;  // (0.0f, 0.0f)
#pragma unroll
            for (int i = 0; i < 8; i++) ffma2(acc, wj[jj][i], ipr[i]);
#pragma unroll
            for (int r = 0; r < 4; r++) ffma2(acc, lj[jj][r], upr[r]);
            float lo, hi;
            unpack2(lo, hi, acc);
            res[jj] = lo + hi;
        }

        float4 o;
        o.x = fmaf(0.1f, res[0], 0.9f * h4.x);
        o.y = fmaf(0.1f, res[1], 0.9f * h4.y);
        o.z = fmaf(0.1f, res[2], 0.9f * h4.z);
        o.w = fmaf(0.1f, res[3], 0.9f * h4.w);
        *(float4*)(nh_out + b * HID + j0) = o;
    }
}

// ---------------------------------------------------------------------------
// K3: partial out over one H-chunk of 1024.
// grid = (BATCH/4, HSPLIT) = 1024 blocks, single pass, accurate tanh.
// ---------------------------------------------------------------------------
__global__ void __launch_bounds__(256) k_out(const float* __restrict__ nh,
                                             const float* __restrict__ Wout) {
    const int t = threadIdx.x;
    const int bbase = blockIdx.x * 4;
    const int hs = blockIdx.y;
    const int j = hs * (HID / HSPLIT) + t * 4;

    float4 w4[4];
#pragma unroll
    for (int o = 0; o < 4; o++)
        w4[o] = *(const float4*)(Wout + o * HID + j);

    float acc[4][4];
#pragma unroll
    for (int bl = 0; bl < 4; bl++) {
        float4 x = *(const float4*)(nh + (bbase + bl) * HID + j);
        float t0 = fast_tanh(x.x);
        float t1 = fast_tanh(x.y);
        float t2 = fast_tanh(x.z);
        float t3 = fast_tanh(x.w);
#pragma unroll
        for (int o = 0; o < 4; o++) {
            float a = t0 * w4[o].x;
            a = fmaf(t1, w4[o].y, a);
            a = fmaf(t2, w4[o].z, a);
            a = fmaf(t3, w4[o].w, a);
            acc[bl][o] = a;
        }
    }

#pragma unroll
    for (int bl = 0; bl < 4; bl++)
#pragma unroll
        for (int o = 0; o < 4; o++)
#pragma unroll
            for (int off = 16; off > 0; off >>= 1)
                acc[bl][o] += __shfl_xor_sync(0xffffffffu, acc[bl][o], off);

    __shared__ float red[8][16];
    const int lane = t & 31, w = t >> 5;
    if (lane == 0) {
#pragma unroll
        for (int bl = 0; bl < 4; bl++)
#pragma unroll
            for (int o = 0; o < 4; o++)
                red[w][bl * 4 + o] = acc[bl][o];
    }
    __syncthreads();
    if (t < 16) {
        float s = 0.0f;
#pragma unroll
        for (int w2 = 0; w2 < 8; w2++) s += red[w2][t];
        const int bl = t >> 2, o = t & 3;
        g_out_part[hs][(bbase + bl) * NOUT + o] = s;
    }
}

// ---------------------------------------------------------------------------
// K3b: combine out partials. 2048 outputs.
// ---------------------------------------------------------------------------
__global__ void __launch_bounds__(256) k_out_final(float* __restrict__ out) {
    const int idx = blockIdx.x * 256 + threadIdx.x;
    if (idx < BATCH * NOUT) {
        float s = 0.0f;
#pragma unroll
        for (int hs = 0; hs < HSPLIT; hs++) s += g_out_part[hs][idx];
        out[idx] = s * (1.0f / (float)HID);
    }
}

extern "C" void kernel_launch(void* const* d_in, const int* in_sizes, int n_in,
                              void* d_out, int out_size) {
    const float* input  = (const float*)d_in[0];  // [512,16]
    const float* hidden = (const float*)d_in[1];  // [512,8192]
    const float* Win    = (const float*)d_in[2];  // [8192,16]
    const float* L      = (const float*)d_in[3];  // [8192,8]
    const float* R      = (const float*)d_in[4];  // [8,8192]
    const float* Wout   = (const float*)d_in[5];  // [4,8192]

    float* out = (float*)d_out;                   // [512,4] then [512,8192]
    float* nh  = out + BATCH * NOUT;

    k_rank<<<dim3(BATCH / 4, HSPLIT), 256>>>(hidden, R);
    k_u_combine<<<(BATCH * RANK + 255) / 256, 256>>>();
    k_update<<<dim3(HID / 64, BSPLIT), 256>>>(input, hidden, Win, L, nh);
    k_out<<<dim3(BATCH / 4, HSPLIT), 256>>>(nh, Wout);
    k_out_final<<<(BATCH * NOUT + 255) / 256, 256>>>(out);
}